// round 15
// baseline (speedup 1.0000x reference)
#include <cuda_runtime.h>
#include <cuda_bf16.h>
#include <cstdint>
#include <math.h>

// ---------------- scratch -------------------------------------------------
__device__ __nv_bfloat16 g_fh [2 * 2048 * 1024]; // box|part feats hi
__device__ __nv_bfloat16 g_fl [2 * 2048 * 1024]; // lo
__device__ __nv_bfloat16 g_wh [2 * 1024 * 1024]; // Wq|Wk hi
__device__ __nv_bfloat16 g_wl [2 * 1024 * 1024];
__device__ __nv_bfloat16 g_cwh[1024 * 1024];     // conv_w hi
__device__ __nv_bfloat16 g_cwl[1024 * 1024];
__device__ __nv_bfloat16 g_qkh[2 * 2048 * 1024]; // q|k hi
__device__ __nv_bfloat16 g_qkl[2 * 2048 * 1024];
__device__ __nv_bfloat16 g_pwh[1024 * 2048];     // pwT hi  [GE, P]
__device__ __nv_bfloat16 g_pwl[1024 * 2048];
__device__ float         g_L  [2048 * 16 * 1024]; // logits / softmax

// ---------------- helpers -------------------------------------------------
__device__ __forceinline__ uint32_t smem_u32(const void* p) {
    uint32_t a;
    asm("{ .reg .u64 t; cvta.to.shared.u64 t, %1; cvt.u32.u64 %0, t; }"
        : "=r"(a) : "l"(p));
    return a;
}
__device__ __forceinline__ uint32_t pack_bf(float lo, float hi) {
    uint32_t r;
    asm("cvt.rn.bf16x2.f32 %0, %1, %2;" : "=r"(r) : "f"(hi), "f"(lo));
    return r;
}
#define STS64(a, x, y) \
    asm volatile("st.shared.v2.b32 [%0], {%1, %2};" :: "r"(a), "r"(x), "r"(y) : "memory")
#define STS128(a, v) \
    asm volatile("st.shared.v4.b32 [%0], {%1, %2, %3, %4};" \
                 :: "r"(a), "r"((v).x), "r"((v).y), "r"((v).z), "r"((v).w) : "memory")

__device__ __forceinline__ void ldsm4(uint32_t* r, uint32_t addr) {
    asm volatile("ldmatrix.sync.aligned.m8n8.x4.shared.b16 {%0,%1,%2,%3}, [%4];"
        : "=r"(r[0]), "=r"(r[1]), "=r"(r[2]), "=r"(r[3]) : "r"(addr));
}
__device__ __forceinline__ void mma16816(float* d, const uint32_t* a, const uint32_t* b) {
    asm volatile(
        "mma.sync.aligned.m16n8k16.row.col.f32.bf16.bf16.f32 "
        "{%0,%1,%2,%3}, {%4,%5,%6,%7}, {%8,%9}, {%0,%1,%2,%3};"
        : "+f"(d[0]), "+f"(d[1]), "+f"(d[2]), "+f"(d[3])
        : "r"(a[0]), "r"(a[1]), "r"(a[2]), "r"(a[3]), "r"(b[0]), "r"(b[1]));
}
// packed fp32x2 ops (sm_100+)
__device__ __forceinline__ void ffma2(unsigned long long& d,
                                      unsigned long long a, unsigned long long b) {
    asm("fma.rn.f32x2 %0, %1, %2, %0;" : "+l"(d) : "l"(a), "l"(b));
}
__device__ __forceinline__ unsigned long long pack2(float x, float y) {
    unsigned long long r;
    asm("mov.b64 %0, {%1, %2};" : "=l"(r) : "f"(x), "f"(y));
    return r;
}
__device__ __forceinline__ void unpack2(unsigned long long v, float& x, float& y) {
    asm("mov.b64 {%0, %1}, %2;" : "=f"(x), "=f"(y) : "l"(v));
}
// split a pair of fp32 into (hi bf16x2, lo bf16x2)
__device__ __forceinline__ void split2(float x, float y, uint32_t& h, uint32_t& l) {
    h = pack_bf(x, y);
    float hx = __uint_as_float(h << 16);
    float hy = __uint_as_float(h & 0xFFFF0000u);
    l = pack_bf(x - hx, y - hy);
}

// ---------------- fp32 -> bf16 hi/lo plane split --------------------------
__global__ __launch_bounds__(256) void split_kernel(
    const float* __restrict__ src, __nv_bfloat16* __restrict__ hi,
    __nv_bfloat16* __restrict__ lo, int n)
{
    int i = (blockIdx.x * 256 + threadIdx.x) * 8;
    if (i >= n) return;
    float4 a = *(const float4*)(src + i);
    float4 b = *(const float4*)(src + i + 4);
    uint4 h, l;
    split2(a.x, a.y, h.x, l.x);
    split2(a.z, a.w, h.y, l.y);
    split2(b.x, b.y, h.z, l.z);
    split2(b.z, b.w, h.w, l.w);
    *(uint4*)(hi + i) = h;
    *(uint4*)(lo + i) = l;
}

// ---------------- bf16-split tensor-core GEMM -----------------------------
// C[m,n] = alpha * sum_k A[m,k]*B[n,k] + bias[n]
// A16/B16: operand is pre-split bf16 hi plane (lo at +planeX elems).
// OSPLIT: C written as bf16 hi/lo planes instead of fp32.
template <int BN, bool A16, bool B16, bool OSPLIT>
__global__ __launch_bounds__(256) void tgemm(
    const void* __restrict__ Av, const void* __restrict__ Bv,
    const float* __restrict__ bias, void* __restrict__ Cv,
    int K, int lda, int ldb, int ldc,
    long long sA1, long long sA2, long long sB1, long long sB2,
    long long sC1, long long sC2, long long sBias1, long long sBias2,
    int ngroup, float alpha,
    long long planeA, long long planeB, long long planeC)
{
    constexpr int WGM = (BN == 128) ? 4 : 8;
    constexpr int WGN = (BN == 128) ? 2 : 1;
    constexpr int WTM = 128 / WGM;
    constexpr int WTN = BN / WGN;
    constexpr int MB  = WTM / 16;
    constexpr int NB  = WTN / 8;
    constexpr int NB2 = WTN / 16;
    constexpr int A_MAT = 128 * 80;
    constexpr int B_MAT = BN * 80;
    constexpr int BUFSZ = 2 * A_MAT + 2 * B_MAT;
    constexpr int NA4 = 4;          // fp32 A: float4 per thread
    constexpr int NB4 = BN / 32;    // fp32 B
    constexpr int GA  = 2;          // bf16 A: uint4-pair groups per thread
    constexpr int GB  = BN / 64;    // bf16 B

    extern __shared__ char smem[];
    const uint32_t sb = smem_u32(smem);

    const int t = threadIdx.x;
    const int wid = t >> 5, lane = t & 31;
    const int wm = wid % WGM, wn = wid / WGM;

    const int z = blockIdx.z;
    const int bb = z / ngroup;
    const int gg = z - bb * ngroup;

    const float* Af = nullptr;
    const __nv_bfloat16* Abf = nullptr;
    if (A16) Abf = (const __nv_bfloat16*)Av + bb * sA1 + gg * sA2;
    else     Af  = (const float*)Av + bb * sA1 + gg * sA2;
    const float* Bf = nullptr;
    const __nv_bfloat16* Bbf = nullptr;
    if (B16) Bbf = (const __nv_bfloat16*)Bv + bb * sB1 + gg * sB2;
    else     Bf  = (const float*)Bv + bb * sB1 + gg * sB2;
    float* Cf = nullptr;
    __nv_bfloat16* Cbf = nullptr;
    if (OSPLIT) Cbf = (__nv_bfloat16*)Cv + bb * sC1 + gg * sC2;
    else        Cf  = (float*)Cv + bb * sC1 + gg * sC2;
    if (bias) bias += bb * sBias1 + gg * sBias2;

    const int m0 = blockIdx.y * 128;
    const int n0 = blockIdx.x * BN;

    float4 pa[A16 ? 1 : NA4];
    float4 pb[B16 ? 1 : NB4];
    uint4 pah[A16 ? GA : 1], pal[A16 ? GA : 1];
    uint4 pbh[B16 ? GB : 1], pbl[B16 ? GB : 1];

    auto ldgA = [&](int c) {
        const int k0 = c * 32;
        if (A16) {
#pragma unroll
            for (int r = 0; r < GA; r++) {
                int f = r * 256 + t, row = f >> 2, s8 = f & 3;
                const __nv_bfloat16* p = Abf + (size_t)(m0 + row) * lda + k0 + s8 * 8;
                pah[r] = *(const uint4*)p;
                pal[r] = *(const uint4*)(p + planeA);
            }
        } else {
#pragma unroll
            for (int r = 0; r < NA4; r++) {
                int f = r * 256 + t, row = f >> 3, seg = f & 7;
                pa[r] = *(const float4*)(Af + (size_t)(m0 + row) * lda + k0 + seg * 4);
            }
        }
    };
    auto ldgB = [&](int c) {
        const int k0 = c * 32;
        if (B16) {
#pragma unroll
            for (int r = 0; r < GB; r++) {
                int f = r * 256 + t, row = f >> 2, s8 = f & 3;
                const __nv_bfloat16* p = Bbf + (size_t)(n0 + row) * ldb + k0 + s8 * 8;
                pbh[r] = *(const uint4*)p;
                pbl[r] = *(const uint4*)(p + planeB);
            }
        } else {
#pragma unroll
            for (int r = 0; r < NB4; r++) {
                int f = r * 256 + t, row = f >> 3, seg = f & 7;
                pb[r] = *(const float4*)(Bf + (size_t)(n0 + row) * ldb + k0 + seg * 4);
            }
        }
    };
    auto sts = [&](int buf) {
        const uint32_t base = sb + buf * BUFSZ;
        if (A16) {
#pragma unroll
            for (int r = 0; r < GA; r++) {
                int f = r * 256 + t, row = f >> 2, s8 = f & 3;
                uint32_t off = base + row * 80 + s8 * 16;
                STS128(off, pah[r]);
                STS128(off + A_MAT, pal[r]);
            }
        } else {
#pragma unroll
            for (int r = 0; r < NA4; r++) {
                int f = r * 256 + t, row = f >> 3, seg = f & 7;
                float4 v = pa[r];
                uint32_t h01, l01, h23, l23;
                split2(v.x, v.y, h01, l01);
                split2(v.z, v.w, h23, l23);
                uint32_t off = base + row * 80 + seg * 8;
                STS64(off, h01, h23);
                STS64(off + A_MAT, l01, l23);
            }
        }
        if (B16) {
#pragma unroll
            for (int r = 0; r < GB; r++) {
                int f = r * 256 + t, row = f >> 2, s8 = f & 3;
                uint32_t off = base + 2 * A_MAT + row * 80 + s8 * 16;
                STS128(off, pbh[r]);
                STS128(off + B_MAT, pbl[r]);
            }
        } else {
#pragma unroll
            for (int r = 0; r < NB4; r++) {
                int f = r * 256 + t, row = f >> 3, seg = f & 7;
                float4 v = pb[r];
                uint32_t h01, l01, h23, l23;
                split2(v.x, v.y, h01, l01);
                split2(v.z, v.w, h23, l23);
                uint32_t off = base + 2 * A_MAT + row * 80 + seg * 8;
                STS64(off, h01, h23);
                STS64(off + B_MAT, l01, l23);
            }
        }
    };

    float acc[MB][NB][4];
#pragma unroll
    for (int i = 0; i < MB; i++)
#pragma unroll
        for (int j = 0; j < NB; j++)
#pragma unroll
            for (int q = 0; q < 4; q++) acc[i][j][q] = 0.f;

    const uint32_t a_lane = (uint32_t)((lane & 15) * 80 + (lane >> 4) * 16);
    const uint32_t b_lane = (uint32_t)(((lane & 7) + ((lane >> 4) << 3)) * 80
                                       + ((lane >> 3) & 1) * 16);

    auto compute = [&](int buf) {
        const uint32_t base = sb + buf * BUFSZ;
#pragma unroll
        for (int ks = 0; ks < 2; ks++) {
            const uint32_t ko = ks * 32;
            uint32_t Ah[MB][4], Al[MB][4], Bh[NB][2], Bl[NB][2];
#pragma unroll
            for (int mb = 0; mb < MB; mb++) {
                uint32_t ad = base + (wm * WTM + mb * 16) * 80 + a_lane + ko;
                ldsm4(Ah[mb], ad);
                ldsm4(Al[mb], ad + A_MAT);
            }
#pragma unroll
            for (int n2 = 0; n2 < NB2; n2++) {
                uint32_t bd = base + 2 * A_MAT + (wn * WTN + n2 * 16) * 80 + b_lane + ko;
                ldsm4(&Bh[2 * n2][0], bd);
                ldsm4(&Bl[2 * n2][0], bd + B_MAT);
            }
#pragma unroll
            for (int mb = 0; mb < MB; mb++)
#pragma unroll
                for (int nb = 0; nb < NB; nb++) {
                    mma16816(acc[mb][nb], Ah[mb], Bh[nb]);
                    mma16816(acc[mb][nb], Ah[mb], Bl[nb]);
                    mma16816(acc[mb][nb], Al[mb], Bh[nb]);
                }
        }
    };

    const int NC = K >> 5;
    ldgA(0); ldgB(0);
    sts(0);
    if (NC > 1) { ldgA(1); ldgB(1); }
    __syncthreads();

    for (int c = 0; c < NC; c++) {
        compute(c & 1);
        __syncthreads();
        if (c + 1 < NC) {
            sts((c + 1) & 1);
            __syncthreads();
            if (c + 2 < NC) { ldgA(c + 2); ldgB(c + 2); }
        }
    }

    // epilogue
    const int er = lane >> 2, ec = (lane & 3) * 2;
#pragma unroll
    for (int mb = 0; mb < MB; mb++) {
#pragma unroll
        for (int nb = 0; nb < NB; nb++) {
            const int m = m0 + wm * WTM + mb * 16 + er;
            const int n = n0 + wn * WTN + nb * 8 + ec;
            float b0 = 0.f, b1 = 0.f;
            if (bias) { b0 = bias[n]; b1 = bias[n + 1]; }
            float x0 = alpha * acc[mb][nb][0] + b0;
            float y0 = alpha * acc[mb][nb][1] + b1;
            float x1 = alpha * acc[mb][nb][2] + b0;
            float y1 = alpha * acc[mb][nb][3] + b1;
            if (OSPLIT) {
                uint32_t h0, l0, h1, l1;
                split2(x0, y0, h0, l0);
                split2(x1, y1, h1, l1);
                *(uint32_t*)(Cbf + (size_t)m * ldc + n) = h0;
                *(uint32_t*)(Cbf + planeC + (size_t)m * ldc + n) = l0;
                *(uint32_t*)(Cbf + (size_t)(m + 8) * ldc + n) = h1;
                *(uint32_t*)(Cbf + planeC + (size_t)(m + 8) * ldc + n) = l1;
            } else {
                float2 v0 = {x0, y0}, v1 = {x1, y1};
                *(float2*)(Cf + (size_t)m * ldc + n) = v0;
                *(float2*)(Cf + (size_t)(m + 8) * ldc + n) = v1;
            }
        }
    }
}

// ---------------- fused poslogit + softmax (unchanged from R12) -----------
__global__ __launch_bounds__(256) void poslogit_kernel(
    const float* __restrict__ rois, const float* __restrict__ part_rois,
    const float* __restrict__ Wg_w, const float* __restrict__ Wg_b,
    float* __restrict__ L)
{
    __shared__ ulonglong2 wgp[256];
    __shared__ unsigned long long wbp[8];
    __shared__ float red[16][8];

    const int t = threadIdx.x;
    const int w = t >> 5, lane = t & 31;
    {
        const int g2 = t & 7, j = (t >> 3) & 7, i = t >> 6;
        const int r0 = (2 * g2) * 64, r1 = (2 * g2 + 1) * 64;
        ulonglong2 wv;
        wv.x = pack2(Wg_w[r0 + i * 16 + j],     Wg_w[r1 + i * 16 + j]);
        wv.y = pack2(Wg_w[r0 + i * 16 + 8 + j], Wg_w[r1 + i * 16 + 8 + j]);
        wgp[t] = wv;
        if (t < 8) wbp[t] = pack2(Wg_b[2 * t], Wg_b[2 * t + 1]);
    }

    const int n = blockIdx.x;
    const int b = blockIdx.y;
    const int ng = b * 1024 + n;

    const float xmin = rois[ng * 5 + 1];
    const float ymin = rois[ng * 5 + 2];
    const float xmax = rois[ng * 5 + 3];
    const float ymax = rois[ng * 5 + 4];
    const float bw = xmax - xmin + 1.f;
    const float bh = ymax - ymin + 1.f;
    const float cx = 0.5f * (xmin + xmax);
    const float cy = 0.5f * (ymin + ymax);

    float pos[4][4];
#pragma unroll
    for (int pp = 0; pp < 4; pp++) {
        const int pg = b * 1024 + pp * 256 + t;
        const float pxmin = part_rois[pg * 5 + 1];
        const float pymin = part_rois[pg * 5 + 2];
        const float pxmax = part_rois[pg * 5 + 3];
        const float pymax = part_rois[pg * 5 + 4];
        const float pw = pxmax - pxmin + 1.f;
        const float ph = pymax - pymin + 1.f;
        const float pcx = 0.5f * (pxmin + pxmax);
        const float pcy = 0.5f * (pymin + pymax);
        float dx = fabsf((cx - pcx) / bw);
        float dy = fabsf((cy - pcy) / bh);
        pos[pp][0] = __logf(fmaxf(dx, 1e-3f));
        pos[pp][1] = __logf(fmaxf(dy, 1e-3f));
        pos[pp][2] = __logf(pw / bw);
        pos[pp][3] = __logf(ph / bh);
    }
    __syncthreads();

    const float inv_em[8] = {
        1.0f, 0.42169651f, 0.17782794f, 0.074989424f,
        0.031622777f, 0.013335215f, 0.0056234133f, 0.0023713737f};

    unsigned long long acc2[4][8];
#pragma unroll
    for (int pp = 0; pp < 4; pp++)
#pragma unroll
        for (int g2 = 0; g2 < 8; g2++) acc2[pp][g2] = wbp[g2];

#pragma unroll
    for (int i = 0; i < 4; i++) {
#pragma unroll
        for (int j = 0; j < 8; j++) {
            unsigned long long s2[4], c2[4];
#pragma unroll
            for (int pp = 0; pp < 4; pp++) {
                float s, c;
                __sincosf(100.f * pos[pp][i] * inv_em[j], &s, &c);
                s2[pp] = pack2(s, s);
                c2[pp] = pack2(c, c);
            }
            const ulonglong2* wrow = &wgp[(i * 8 + j) * 8];
#pragma unroll
            for (int g2 = 0; g2 < 8; g2++) {
                ulonglong2 wv = wrow[g2];
#pragma unroll
                for (int pp = 0; pp < 4; pp++) {
                    ffma2(acc2[pp][g2], s2[pp], wv.x);
                    ffma2(acc2[pp][g2], c2[pp], wv.y);
                }
            }
        }
    }

    const size_t base = ((size_t)ng * 16) * 1024 + t;
#pragma unroll
    for (int pp = 0; pp < 4; pp++) {
#pragma unroll
        for (int g2 = 0; g2 < 8; g2++) {
            float a0, a1;
            unpack2(acc2[pp][g2], a0, a1);
            a0 = __logf(fmaxf(a0, 1e-6f)) + L[base + (size_t)(2 * g2) * 1024 + pp * 256];
            a1 = __logf(fmaxf(a1, 1e-6f)) + L[base + (size_t)(2 * g2 + 1) * 1024 + pp * 256];
            acc2[pp][g2] = pack2(a0, a1);
        }
    }

#pragma unroll
    for (int g2 = 0; g2 < 8; g2++) {
        float m0 = -1e30f, m1 = -1e30f;
#pragma unroll
        for (int pp = 0; pp < 4; pp++) {
            float a0, a1;
            unpack2(acc2[pp][g2], a0, a1);
            m0 = fmaxf(m0, a0);
            m1 = fmaxf(m1, a1);
        }
#pragma unroll
        for (int o = 16; o > 0; o >>= 1) {
            m0 = fmaxf(m0, __shfl_xor_sync(0xFFFFFFFFu, m0, o));
            m1 = fmaxf(m1, __shfl_xor_sync(0xFFFFFFFFu, m1, o));
        }
        if (lane == 0) { red[2 * g2][w] = m0; red[2 * g2 + 1][w] = m1; }
    }
    __syncthreads();
    float mx[16];
#pragma unroll
    for (int g = 0; g < 16; g++) {
        float4 r0 = *(const float4*)&red[g][0];
        float4 r1 = *(const float4*)&red[g][4];
        mx[g] = fmaxf(fmaxf(fmaxf(r0.x, r0.y), fmaxf(r0.z, r0.w)),
                      fmaxf(fmaxf(r1.x, r1.y), fmaxf(r1.z, r1.w)));
    }
    __syncthreads();

#pragma unroll
    for (int g2 = 0; g2 < 8; g2++) {
        float s0 = 0.f, s1 = 0.f;
#pragma unroll
        for (int pp = 0; pp < 4; pp++) {
            float a0, a1;
            unpack2(acc2[pp][g2], a0, a1);
            a0 = __expf(a0 - mx[2 * g2]);
            a1 = __expf(a1 - mx[2 * g2 + 1]);
            acc2[pp][g2] = pack2(a0, a1);
            s0 += a0;
            s1 += a1;
        }
#pragma unroll
        for (int o = 16; o > 0; o >>= 1) {
            s0 += __shfl_xor_sync(0xFFFFFFFFu, s0, o);
            s1 += __shfl_xor_sync(0xFFFFFFFFu, s1, o);
        }
        if (lane == 0) { red[2 * g2][w] = s0; red[2 * g2 + 1][w] = s1; }
    }
    __syncthreads();
#pragma unroll
    for (int g = 0; g < 16; g++) {
        float4 r0 = *(const float4*)&red[g][0];
        float4 r1 = *(const float4*)&red[g][4];
        mx[g] = 1.f / (r0.x + r0.y + r0.z + r0.w + r1.x + r1.y + r1.z + r1.w);
    }

#pragma unroll
    for (int pp = 0; pp < 4; pp++) {
#pragma unroll
        for (int g2 = 0; g2 < 8; g2++) {
            float a0, a1;
            unpack2(acc2[pp][g2], a0, a1);
            L[base + (size_t)(2 * g2) * 1024 + pp * 256]     = a0 * mx[2 * g2];
            L[base + (size_t)(2 * g2 + 1) * 1024 + pp * 256] = a1 * mx[2 * g2 + 1];
        }
    }
}

// ---------------- host ----------------------------------------------------
extern "C" void kernel_launch(void* const* d_in, const int* in_sizes, int n_in,
                              void* d_out, int out_size)
{
    const float* rois       = (const float*)d_in[0];
    const float* part_rois  = (const float*)d_in[1];
    const float* box_feats  = (const float*)d_in[2];
    const float* part_feats = (const float*)d_in[3];
    const float* Wg_w       = (const float*)d_in[4];
    const float* Wg_b       = (const float*)d_in[5];
    const float* Wq_w       = (const float*)d_in[6];
    const float* Wq_b       = (const float*)d_in[7];
    const float* Wk_w       = (const float*)d_in[8];
    const float* Wk_b       = (const float*)d_in[9];
    const float* conv_w     = (const float*)d_in[10];
    const float* conv_b     = (const float*)d_in[11];
    float* out = (float*)d_out;

    __nv_bfloat16 *fh, *fl, *wh, *wl, *cwh, *cwl, *qkh, *qkl, *pwh, *pwl;
    float* L;
    cudaGetSymbolAddress((void**)&fh,  g_fh);
    cudaGetSymbolAddress((void**)&fl,  g_fl);
    cudaGetSymbolAddress((void**)&wh,  g_wh);
    cudaGetSymbolAddress((void**)&wl,  g_wl);
    cudaGetSymbolAddress((void**)&cwh, g_cwh);
    cudaGetSymbolAddress((void**)&cwl, g_cwl);
    cudaGetSymbolAddress((void**)&qkh, g_qkh);
    cudaGetSymbolAddress((void**)&qkl, g_qkl);
    cudaGetSymbolAddress((void**)&pwh, g_pwh);
    cudaGetSymbolAddress((void**)&pwl, g_pwl);
    cudaGetSymbolAddress((void**)&L,   g_L);

    const long long pF  = (long long)(fl - fh);
    const long long pW  = (long long)(wl - wh);
    const long long pCW = (long long)(cwl - cwh);
    const long long pQK = (long long)(qkl - qkh);
    const long long pPW = (long long)(pwl - pwh);

    const int SM128 = 2 * (2 * 128 * 80 + 2 * 128 * 80); // 81920
    const int SM64  = 2 * (2 * 128 * 80 + 2 * 64 * 80);  // 61440
    cudaFuncSetAttribute((void*)tgemm<128, true, true, true>,
                         cudaFuncAttributeMaxDynamicSharedMemorySize, SM128);
    cudaFuncSetAttribute((void*)tgemm<128, true, true, false>,
                         cudaFuncAttributeMaxDynamicSharedMemorySize, SM128);
    cudaFuncSetAttribute((void*)tgemm<64, false, true, false>,
                         cudaFuncAttributeMaxDynamicSharedMemorySize, SM64);

    // pre-split all fp32 GEMM inputs into bf16 hi/lo planes
    split_kernel<<<1024, 256>>>(box_feats,  fh,            fl,            2097152);
    split_kernel<<<1024, 256>>>(part_feats, fh + 2097152,  fl + 2097152,  2097152);
    split_kernel<<<512, 256>>>(Wq_w,   wh,            wl,            1048576);
    split_kernel<<<512, 256>>>(Wk_w,   wh + 1048576,  wl + 1048576,  1048576);
    split_kernel<<<512, 256>>>(conv_w, cwh,           cwl,           1048576);

    // merged q & k projections: batch0 q = bf @ Wq^T + b, batch1 k = pf @ Wk^T + b
    {
        long long dBias = (long long)(Wk_b - Wq_b);
        tgemm<128, true, true, true><<<dim3(8, 16, 2), 256, SM128>>>(
            fh, wh, Wq_b, qkh, 1024, 1024, 1024, 1024,
            2097152LL, 0, 1048576LL, 0, 2097152LL, 0, dBias, 0, 1, 1.f,
            pF, pW, pQK);
    }

    // pwT = conv_w @ part_feats^T  -> [GE, P] split planes
    tgemm<128, true, true, true><<<dim3(16, 8, 1), 256, SM128>>>(
        cwh, fh + 2097152, nullptr, pwh, 1024, 1024, 1024, 2048,
        0, 0, 0, 0, 0, 0, 0, 0, 1, 1.f,
        pCW, pF, pPW);

    // att/16 into L: 32 batches (b,g): M=1024 N=1024 K=64
    tgemm<128, true, true, false><<<dim3(8, 8, 32), 256, SM128>>>(
        qkh, qkh + 2097152, nullptr, L, 64, 1024, 1024, 16384,
        1048576LL, 64LL, 1048576LL, 64LL,
        16777216LL, 1024LL, 0LL, 0LL, 16, 1.f / 16.f,
        pQK, pQK, 0);

    // L = softmax(att + log(posfeat))  — fused, one block per (n,b)
    poslogit_kernel<<<dim3(1024, 2), 256>>>(rois, part_rois, Wg_w, Wg_b, L);

    // rel = sm @ pwT^T + conv_b: 32 batches: M=1024 N=64 K=1024
    tgemm<64, false, true, false><<<dim3(1, 8, 32), 256, SM64>>>(
        L, pwh, conv_b, out, 1024, 16384, 2048, 1024,
        16777216LL, 1024LL, 1024LL, 131072LL,
        1048576LL, 64LL, 0LL, 64LL, 16, 1.f,
        0, pPW, 0);
}